// round 5
// baseline (speedup 1.0000x reference)
#include <cuda_runtime.h>
#include <cuda_bf16.h>
#include <cstdint>

#define BATCH 4
#define CCH   256
#define NSEQ  4096
#define HDIM  128
#define LDP   136                  // padded smem row stride (bf16): 272B, ldmatrix conflict-free
#define TILEE (128*LDP)            // elems per 128-row smem tile
#define NT    512                  // threads per CTA

// ---------------- device scratch ----------------
__device__ __align__(16) __nv_bfloat16 g_Ahi[BATCH*NSEQ*HDIM];
__device__ __align__(16) __nv_bfloat16 g_Alo[BATCH*NSEQ*HDIM];
__device__ __align__(16) __nv_bfloat16 g_Bhi[BATCH*NSEQ*HDIM];
__device__ __align__(16) __nv_bfloat16 g_Blo[BATCH*NSEQ*HDIM];
__device__ __align__(16) float         g_diag[BATCH*NSEQ];

// ---------------- helpers ----------------
static __device__ __forceinline__ uint32_t smem_u32(const void* p){
  return (uint32_t)__cvta_generic_to_shared(p);
}
static __device__ __forceinline__ void ldsm4(uint32_t&r0,uint32_t&r1,uint32_t&r2,uint32_t&r3,uint32_t a){
  asm volatile("ldmatrix.sync.aligned.m8n8.x4.shared.b16 {%0,%1,%2,%3}, [%4];"
    : "=r"(r0),"=r"(r1),"=r"(r2),"=r"(r3) : "r"(a));
}
static __device__ __forceinline__ void ldsm4t(uint32_t&r0,uint32_t&r1,uint32_t&r2,uint32_t&r3,uint32_t a){
  asm volatile("ldmatrix.sync.aligned.m8n8.x4.trans.shared.b16 {%0,%1,%2,%3}, [%4];"
    : "=r"(r0),"=r"(r1),"=r"(r2),"=r"(r3) : "r"(a));
}
static __device__ __forceinline__ void mma16816(float* c,
    uint32_t a0,uint32_t a1,uint32_t a2,uint32_t a3,uint32_t b0,uint32_t b1){
  asm volatile("mma.sync.aligned.m16n8k16.row.col.f32.bf16.bf16.f32 "
    "{%0,%1,%2,%3}, {%4,%5,%6,%7}, {%8,%9}, {%0,%1,%2,%3};"
    : "+f"(c[0]),"+f"(c[1]),"+f"(c[2]),"+f"(c[3])
    : "r"(a0),"r"(a1),"r"(a2),"r"(a3),"r"(b0),"r"(b1));
}
static __device__ __forceinline__ uint32_t packbf(float x, float y){
  __nv_bfloat16 a=__float2bfloat16(x), b=__float2bfloat16(y);
  return ((uint32_t)__bfloat16_as_ushort(b)<<16)|(uint32_t)__bfloat16_as_ushort(a);
}
static __device__ __forceinline__ void split_store(__nv_bfloat16* hi, __nv_bfloat16* lo,
                                                   int off, float4 v){
  __nv_bfloat16 h0=__float2bfloat16(v.x),h1=__float2bfloat16(v.y);
  __nv_bfloat16 h2=__float2bfloat16(v.z),h3=__float2bfloat16(v.w);
  uint2 ph, pl;
  ph.x = ((uint32_t)__bfloat16_as_ushort(h1)<<16)|__bfloat16_as_ushort(h0);
  ph.y = ((uint32_t)__bfloat16_as_ushort(h3)<<16)|__bfloat16_as_ushort(h2);
  pl.x = packbf(v.x-__bfloat162float(h0), v.y-__bfloat162float(h1));
  pl.y = packbf(v.z-__bfloat162float(h2), v.w-__bfloat162float(h3));
  *(uint2*)(hi + off) = ph;
  *(uint2*)(lo + off) = pl;
}
static __device__ __forceinline__ void cpa16(uint32_t s, const void* g){
  asm volatile("cp.async.cg.shared.global [%0],[%1],16;"::"r"(s),"l"(g));
}

// ====================================================================
// Phase 1: mapped[b,n,h] = sum_c X[b,c,n]*W[h,c] + bias[h], bf16x3 split,
// stored as hi/lo bf16 pairs at [b][n][h].
// 16 warps, warp tile 16(n) x 64(h). A = X^T via ldmatrix.trans.
// ====================================================================
__global__ void __launch_bounds__(NT,1) map_kernel(
    const float* __restrict__ Xa, const float* __restrict__ Xb,
    const float* __restrict__ Wa, const float* __restrict__ ba,
    const float* __restrict__ Wb, const float* __restrict__ bb)
{
  extern __shared__ __nv_bfloat16 sm[];
  __nv_bfloat16* sXhi = sm;                // [c:128][LDP]
  __nv_bfloat16* sXlo = sm + TILEE;
  __nv_bfloat16* sWhi = sm + 2*TILEE;      // [h:128][LDP]
  __nv_bfloat16* sWlo = sm + 3*TILEE;

  const int t = threadIdx.x, warp = t>>5, lane = t&31;
  const int ntile = blockIdx.x, b = blockIdx.y, sel = blockIdx.z;
  const float* X    = sel ? Xb : Xa;
  const float* W    = sel ? Wb : Wa;
  const float* bias = sel ? bb : ba;
  __nv_bfloat16* Ohi = sel ? g_Bhi : g_Ahi;
  __nv_bfloat16* Olo = sel ? g_Blo : g_Alo;
  const int n0 = ntile*128;
  const int R  = (warp>>1)*16;       // warp row block (n), 8 blocks of 16
  const int CW = (warp&1)*64;        // warp col block (h)

  float acc[8][4];
  #pragma unroll
  for (int f=0;f<8;f++){acc[f][0]=0.f;acc[f][1]=0.f;acc[f][2]=0.f;acc[f][3]=0.f;}

  for (int cc=0; cc<2; cc++){        // two K-chunks of 128 channels
    // X chunk [c:128][n:128], coalesced along n
    const float* src = X + ((size_t)b*CCH + (size_t)cc*128)*NSEQ + n0;
    #pragma unroll
    for (int it=0; it<8; it++){
      int idx = t + it*NT;
      int row = idx>>5, c4 = idx&31;
      float4 v = *(const float4*)(src + (size_t)row*NSEQ + (c4<<2));
      split_store(sXhi, sXlo, row*LDP + (c4<<2), v);
    }
    // W chunk [h:128][c:128]
    const float* srcW = W + cc*128;
    #pragma unroll
    for (int it=0; it<8; it++){
      int idx = t + it*NT;
      int row = idx>>5, c4 = idx&31;
      float4 v = *(const float4*)(srcW + (size_t)row*CCH + (c4<<2));
      split_store(sWhi, sWlo, row*LDP + (c4<<2), v);
    }
    __syncthreads();

    #pragma unroll
    for (int seg=0; seg<3; seg++){
      const __nv_bfloat16* A  = (seg==2)? sXlo : sXhi;
      const __nv_bfloat16* Bm = (seg==1)? sWlo : sWhi;
      uint32_t ab = smem_u32(A), bbs = smem_u32(Bm);
      #pragma unroll
      for (int kk=0; kk<8; kk++){
        int arow = (kk<<4) + (lane&7) + ((lane>>4)<<3);       // c row in tile
        uint32_t a0,a1,a2,a3;
        ldsm4t(a0,a1,a2,a3,
               ab + (uint32_t)((arow*LDP + R + (((lane>>3)&1)<<3))<<1));
        #pragma unroll
        for (int j=0;j<4;j++){
          int brow = CW + (j<<4) + (lane&15);                  // h row
          uint32_t b0,b1,b2,b3;
          ldsm4(b0,b1,b2,b3, bbs + (uint32_t)((brow*LDP + (kk<<4) + ((lane>>4)<<3))<<1));
          mma16816(acc[2*j],   a0,a1,a2,a3, b0,b2);
          mma16816(acc[2*j+1], a0,a1,a2,a3, b1,b3);
        }
      }
    }
    __syncthreads();
  }

  // epilogue: +bias, split hi/lo, store [b][n][h]
  const size_t rowbase = (size_t)b*NSEQ + n0;
  const int r0 = R + (lane>>2);
  #pragma unroll
  for (int f=0; f<8; f++){
    int h = CW + (f<<3) + ((lane&3)<<1);
    float bv0 = bias[h], bv1 = bias[h+1];
    float m00=acc[f][0]+bv0, m01=acc[f][1]+bv1;
    float m10=acc[f][2]+bv0, m11=acc[f][3]+bv1;
    __nv_bfloat16 h00=__float2bfloat16(m00), h01=__float2bfloat16(m01);
    __nv_bfloat16 h10=__float2bfloat16(m10), h11=__float2bfloat16(m11);
    int o0 = (int)((rowbase + r0    )*HDIM) + h;
    int o1 = (int)((rowbase + r0 + 8)*HDIM) + h;
    *(uint32_t*)(Ohi+o0) = ((uint32_t)__bfloat16_as_ushort(h01)<<16)|__bfloat16_as_ushort(h00);
    *(uint32_t*)(Ohi+o1) = ((uint32_t)__bfloat16_as_ushort(h11)<<16)|__bfloat16_as_ushort(h10);
    *(uint32_t*)(Olo+o0) = packbf(m00-__bfloat162float(h00), m01-__bfloat162float(h01));
    *(uint32_t*)(Olo+o1) = packbf(m10-__bfloat162float(h10), m11-__bfloat162float(h11));
  }
}

// ====================================================================
// Phase 2: per row n: rowsum = sum_x exp(S[n,x]), diag = exp(S[n,n])/rowsum.
// S = mapped_a . mapped_b^T (bf16x3, K=128). No max subtraction needed.
// 16 warps, warp tile 16x64, double accumulator sets so exp(tile j-1)
// overlaps MMA(tile j). ONE __syncthreads per tile.
// ====================================================================
static __device__ __forceinline__ void load_pair(uint32_t dh, uint32_t dl,
    const __nv_bfloat16* __restrict__ gh, const __nv_bfloat16* __restrict__ gl,
    size_t rowbase, int t)
{
  #pragma unroll
  for (int it=0; it<4; it++){
    int idx = t + (it<<9);               // 512 threads
    int row = idx>>4, hc = idx&15;
    uint32_t off = (uint32_t)((row*LDP + (hc<<3))<<1);
    const __nv_bfloat16* sh = gh + (rowbase+row)*HDIM + (hc<<3);
    const __nv_bfloat16* sl = gl + (rowbase+row)*HDIM + (hc<<3);
    cpa16(dh + off, sh);
    cpa16(dl + off, sl);
  }
}

__global__ void __launch_bounds__(NT,1) attn_kernel()
{
  extern __shared__ __nv_bfloat16 sm2[];
  __nv_bfloat16* sAhi = sm2;
  __nv_bfloat16* sAlo = sm2 + TILEE;
  // B double buffers (hi,lo per buffer)
  uint32_t sB_hi[2], sB_lo[2];
  sB_hi[0] = smem_u32(sm2 + 2*TILEE);
  sB_lo[0] = smem_u32(sm2 + 3*TILEE);
  sB_hi[1] = smem_u32(sm2 + 4*TILEE);
  sB_lo[1] = smem_u32(sm2 + 5*TILEE);
  __shared__ float sdiag[128];
  __shared__ float srow[2][128];

  const int t = threadIdx.x, warp = t>>5, lane = t&31;
  const int ntile = blockIdx.x, b = blockIdx.y;
  const int n0 = ntile*128;
  const size_t base = (size_t)b*NSEQ;
  const int R  = (warp>>1)*16;
  const int CW = (warp&1)*64;

  // prologue: A tile + B tile 0
  load_pair(smem_u32(sAhi), smem_u32(sAlo), g_Ahi, g_Alo, base + n0, t);
  load_pair(sB_hi[0], sB_lo[0], g_Bhi, g_Blo, base, t);
  asm volatile("cp.async.commit_group;":::"memory");

  const uint32_t aHib = smem_u32(sAhi), aLob = smem_u32(sAlo);
  const int a_row  = (lane&7) + (((lane>>3)&1)<<3);
  const int k_off  = ((lane>>4)<<3);
  const int b_rowL = (lane&15);
  const int cb0    = ((lane&3)<<1);

  float acc[2][8][4];
  float rs[2] = {0.f, 0.f};

  for (int j=0; j<32; j++){
    const int s = j&1;
    asm volatile("cp.async.wait_group 0;":::"memory");  // my tile-j loads done
    __syncthreads();                                    // everyone's done + visible;
                                                        // all warps finished LDSM(j-1)
    if (j+1 < 32){
      load_pair(sB_hi[s^1], sB_lo[s^1], g_Bhi, g_Blo, base + (size_t)(j+1)*128, t);
      asm volatile("cp.async.commit_group;":::"memory");
    }

    // zero this tile's accumulator set
    #pragma unroll
    for (int f=0;f<8;f++){acc[s][f][0]=0.f;acc[s][f][1]=0.f;acc[s][f][2]=0.f;acc[s][f][3]=0.f;}

    // MMA tile j (3 bf16x3 segments) from sB[s]
    #pragma unroll
    for (int seg=0; seg<3; seg++){
      uint32_t ab  = (seg==2)? aLob : aHib;
      uint32_t bbs = (seg==1)? sB_lo[s] : sB_hi[s];
      #pragma unroll
      for (int kk=0; kk<8; kk++){
        uint32_t a0,a1,a2,a3;
        ldsm4(a0,a1,a2,a3,
              ab + (uint32_t)(((R + a_row)*LDP + (kk<<4) + k_off)<<1));
        #pragma unroll
        for (int jj=0;jj<4;jj++){
          int brow = CW + (jj<<4) + b_rowL;
          uint32_t b0,b1,b2,b3;
          ldsm4(b0,b1,b2,b3, bbs + (uint32_t)((brow*LDP + (kk<<4) + k_off)<<1));
          mma16816(acc[s][2*jj],   a0,a1,a2,a3, b0,b2);
          mma16816(acc[s][2*jj+1], a0,a1,a2,a3, b1,b3);
        }
      }
    }

    // exp + row-sum of PREVIOUS tile (overlaps this tile's MMA issue)
    if (j > 0){
      const int ps = s^1;
      const int jexp = j-1;
      const int r0 = R + (lane>>2);
      if (jexp == ntile){
        #pragma unroll
        for (int f=0; f<8; f++){
          int col = CW + (f<<3) + cb0;
          float e0 = __expf(acc[ps][f][0]);
          float e1 = __expf(acc[ps][f][1]);
          float e2 = __expf(acc[ps][f][2]);
          float e3 = __expf(acc[ps][f][3]);
          rs[0] += e0 + e1;
          rs[1] += e2 + e3;
          if (col   == r0  ) sdiag[r0]   = e0;
          if (col+1 == r0  ) sdiag[r0]   = e1;
          if (col   == r0+8) sdiag[r0+8] = e2;
          if (col+1 == r0+8) sdiag[r0+8] = e3;
        }
      } else {
        #pragma unroll
        for (int f=0; f<8; f++){
          float e0 = __expf(acc[ps][f][0]);
          float e1 = __expf(acc[ps][f][1]);
          float e2 = __expf(acc[ps][f][2]);
          float e3 = __expf(acc[ps][f][3]);
          rs[0] += e0 + e1;
          rs[1] += e2 + e3;
        }
      }
    }
  }

  // final tile (31) exp
  {
    const int ps = 31&1;
    const int r0 = R + (lane>>2);
    if (31 == ntile){
      #pragma unroll
      for (int f=0; f<8; f++){
        int col = CW + (f<<3) + cb0;
        float e0 = __expf(acc[ps][f][0]);
        float e1 = __expf(acc[ps][f][1]);
        float e2 = __expf(acc[ps][f][2]);
        float e3 = __expf(acc[ps][f][3]);
        rs[0] += e0 + e1;
        rs[1] += e2 + e3;
        if (col   == r0  ) sdiag[r0]   = e0;
        if (col+1 == r0  ) sdiag[r0]   = e1;
        if (col   == r0+8) sdiag[r0+8] = e2;
        if (col+1 == r0+8) sdiag[r0+8] = e3;
      }
    } else {
      #pragma unroll
      for (int f=0; f<8; f++){
        float e0 = __expf(acc[ps][f][0]);
        float e1 = __expf(acc[ps][f][1]);
        float e2 = __expf(acc[ps][f][2]);
        float e3 = __expf(acc[ps][f][3]);
        rs[0] += e0 + e1;
        rs[1] += e2 + e3;
      }
    }
  }

  // reduce: shfl sums the 4 lanes sharing a row within the warp's 64 cols
  #pragma unroll
  for (int q=0;q<2;q++){
    rs[q] += __shfl_xor_sync(0xffffffffu, rs[q], 1);
    rs[q] += __shfl_xor_sync(0xffffffffu, rs[q], 2);
  }
  if ((lane&3)==0){
    int rr = lane>>2;
    srow[warp&1][R + rr]     = rs[0];
    srow[warp&1][R + 8 + rr] = rs[1];
  }
  __syncthreads();
  if (t < 128){
    float tot = srow[0][t] + srow[1][t];
    g_diag[base + n0 + t] = sdiag[t] / tot;
  }
}

// ====================================================================
// Phase 3: out_a = diag * input_b ; out_b = diag * input_a  (float4)
// ====================================================================
__global__ void __launch_bounds__(256) scale_kernel(
    const float* __restrict__ Xa, const float* __restrict__ Xb, float* __restrict__ out)
{
  const int NF4 = (BATCH*CCH*NSEQ)/4;
  const float4* A4 = (const float4*)Xa;
  const float4* B4 = (const float4*)Xb;
  const float4* D4 = (const float4*)g_diag;
  float4* O = (float4*)out;
  int stride = gridDim.x*blockDim.x;
  for (int i = blockIdx.x*blockDim.x + threadIdx.x; i < 2*NF4; i += stride){
    int sel = (i >= NF4);
    int j = sel ? i - NF4 : i;
    int n4 = j & (NSEQ/4 - 1);
    int bb = (j >> 10) >> 8;
    float4 d = D4[(bb<<10) + n4];
    float4 v = sel ? A4[j] : B4[j];
    float4 o; o.x=v.x*d.x; o.y=v.y*d.y; o.z=v.z*d.z; o.w=v.w*d.w;
    O[i] = o;
  }
}

extern "C" void kernel_launch(void* const* d_in, const int* in_sizes, int n_in,
                              void* d_out, int out_size) {
  const float* Xa = (const float*)d_in[0];
  const float* Xb = (const float*)d_in[1];
  const float* Wa = (const float*)d_in[2];
  const float* ba = (const float*)d_in[3];
  const float* Wb = (const float*)d_in[4];
  const float* bb = (const float*)d_in[5];
  float* out = (float*)d_out;

  const int SMEM_A = 4*TILEE*2;   // 139264 B
  const int SMEM_B = 6*TILEE*2;   // 208896 B
  cudaFuncSetAttribute(map_kernel,  cudaFuncAttributeMaxDynamicSharedMemorySize, SMEM_A);
  cudaFuncSetAttribute(attn_kernel, cudaFuncAttributeMaxDynamicSharedMemorySize, SMEM_B);

  dim3 ga(NSEQ/128, BATCH, 2);
  map_kernel<<<ga, NT, SMEM_A>>>(Xa, Xb, Wa, ba, Wb, bb);
  dim3 gb(NSEQ/128, BATCH);
  attn_kernel<<<gb, NT, SMEM_B>>>();
  scale_kernel<<<2048, 256>>>(Xa, Xb, out);
}

// round 6
// speedup vs baseline: 1.6658x; 1.6658x over previous
#include <cuda_runtime.h>
#include <cuda_bf16.h>
#include <cstdint>

#define BATCH 4
#define CCH   256
#define NSEQ  4096
#define HDIM  128
#define LDP   136                  // padded smem row stride (bf16): 272B, ldmatrix conflict-free
#define TILEE (128*LDP)            // elems per 128-row smem tile

// ---------------- device scratch ----------------
__device__ __align__(16) __nv_bfloat16 g_Ahi[BATCH*NSEQ*HDIM];
__device__ __align__(16) __nv_bfloat16 g_Alo[BATCH*NSEQ*HDIM];
__device__ __align__(16) __nv_bfloat16 g_Bhi[BATCH*NSEQ*HDIM];
__device__ __align__(16) __nv_bfloat16 g_Blo[BATCH*NSEQ*HDIM];
__device__ __align__(16) float         g_diag[BATCH*NSEQ];

// ---------------- helpers ----------------
static __device__ __forceinline__ uint32_t smem_u32(const void* p){
  return (uint32_t)__cvta_generic_to_shared(p);
}
static __device__ __forceinline__ void ldsm4(uint32_t&r0,uint32_t&r1,uint32_t&r2,uint32_t&r3,uint32_t a){
  asm volatile("ldmatrix.sync.aligned.m8n8.x4.shared.b16 {%0,%1,%2,%3}, [%4];"
    : "=r"(r0),"=r"(r1),"=r"(r2),"=r"(r3) : "r"(a));
}
static __device__ __forceinline__ void ldsm4t(uint32_t&r0,uint32_t&r1,uint32_t&r2,uint32_t&r3,uint32_t a){
  asm volatile("ldmatrix.sync.aligned.m8n8.x4.trans.shared.b16 {%0,%1,%2,%3}, [%4];"
    : "=r"(r0),"=r"(r1),"=r"(r2),"=r"(r3) : "r"(a));
}
static __device__ __forceinline__ void mma16816(float* c,
    uint32_t a0,uint32_t a1,uint32_t a2,uint32_t a3,uint32_t b0,uint32_t b1){
  asm volatile("mma.sync.aligned.m16n8k16.row.col.f32.bf16.bf16.f32 "
    "{%0,%1,%2,%3}, {%4,%5,%6,%7}, {%8,%9}, {%0,%1,%2,%3};"
    : "+f"(c[0]),"+f"(c[1]),"+f"(c[2]),"+f"(c[3])
    : "r"(a0),"r"(a1),"r"(a2),"r"(a3),"r"(b0),"r"(b1));
}
static __device__ __forceinline__ uint32_t packbf(float x, float y){
  __nv_bfloat16 a=__float2bfloat16(x), b=__float2bfloat16(y);
  return ((uint32_t)__bfloat16_as_ushort(b)<<16)|(uint32_t)__bfloat16_as_ushort(a);
}
static __device__ __forceinline__ void split_store(__nv_bfloat16* hi, __nv_bfloat16* lo,
                                                   int off, float4 v){
  __nv_bfloat16 h0=__float2bfloat16(v.x),h1=__float2bfloat16(v.y);
  __nv_bfloat16 h2=__float2bfloat16(v.z),h3=__float2bfloat16(v.w);
  uint2 ph, pl;
  ph.x = ((uint32_t)__bfloat16_as_ushort(h1)<<16)|__bfloat16_as_ushort(h0);
  ph.y = ((uint32_t)__bfloat16_as_ushort(h3)<<16)|__bfloat16_as_ushort(h2);
  pl.x = packbf(v.x-__bfloat162float(h0), v.y-__bfloat162float(h1));
  pl.y = packbf(v.z-__bfloat162float(h2), v.w-__bfloat162float(h3));
  *(uint2*)(hi + off) = ph;
  *(uint2*)(lo + off) = pl;
}
static __device__ __forceinline__ void cpa16(uint32_t s, const void* g){
  asm volatile("cp.async.cg.shared.global [%0],[%1],16;"::"r"(s),"l"(g));
}

// ====================================================================
// Phase 1: mapping GEMM — R2 version verbatim (proven: 49us, rel_err ok).
// 8 warps, warp tile 32(n) x 64(h), bf16x3 split.
// ====================================================================
__global__ void __launch_bounds__(256) map_kernel(
    const float* __restrict__ Xa, const float* __restrict__ Xb,
    const float* __restrict__ Wa, const float* __restrict__ ba,
    const float* __restrict__ Wb, const float* __restrict__ bb)
{
  extern __shared__ __nv_bfloat16 sm[];
  __nv_bfloat16* sXhi = sm;                // [c:128][LDP]
  __nv_bfloat16* sXlo = sm + TILEE;
  __nv_bfloat16* sWhi = sm + 2*TILEE;      // [h:128][LDP]
  __nv_bfloat16* sWlo = sm + 3*TILEE;

  const int t = threadIdx.x, warp = t>>5, lane = t&31;
  const int ntile = blockIdx.x, b = blockIdx.y, sel = blockIdx.z;
  const float* X    = sel ? Xb : Xa;
  const float* W    = sel ? Wb : Wa;
  const float* bias = sel ? bb : ba;
  __nv_bfloat16* Ohi = sel ? g_Bhi : g_Ahi;
  __nv_bfloat16* Olo = sel ? g_Blo : g_Alo;
  const int n0 = ntile*128;
  const int R  = (warp>>1)*32;
  const int CW = (warp&1)*64;

  float acc[2][8][4];
  #pragma unroll
  for (int a=0;a<2;a++)
    #pragma unroll
    for (int f=0;f<8;f++){acc[a][f][0]=0.f;acc[a][f][1]=0.f;acc[a][f][2]=0.f;acc[a][f][3]=0.f;}

  for (int cc=0; cc<2; cc++){
    const float* src = X + ((size_t)b*CCH + (size_t)cc*128)*NSEQ + n0;
    #pragma unroll
    for (int it=0; it<16; it++){
      int idx = t + it*256;
      int row = idx>>5, c4 = idx&31;
      float4 v = *(const float4*)(src + (size_t)row*NSEQ + (c4<<2));
      split_store(sXhi, sXlo, row*LDP + (c4<<2), v);
    }
    const float* srcW = W + cc*128;
    #pragma unroll
    for (int it=0; it<16; it++){
      int idx = t + it*256;
      int row = idx>>5, c4 = idx&31;
      float4 v = *(const float4*)(srcW + (size_t)row*CCH + (c4<<2));
      split_store(sWhi, sWlo, row*LDP + (c4<<2), v);
    }
    __syncthreads();

    #pragma unroll
    for (int seg=0; seg<3; seg++){
      const __nv_bfloat16* A  = (seg==2)? sXlo : sXhi;
      const __nv_bfloat16* Bm = (seg==1)? sWlo : sWhi;
      uint32_t ab = smem_u32(A), bbs = smem_u32(Bm);
      #pragma unroll
      for (int kk=0; kk<8; kk++){
        int arow = (kk<<4) + (lane&7) + ((lane>>4)<<3);
        uint32_t A0[4], A1[4];
        ldsm4t(A0[0],A0[1],A0[2],A0[3],
               ab + (uint32_t)((arow*LDP + R      + (((lane>>3)&1)<<3))<<1));
        ldsm4t(A1[0],A1[1],A1[2],A1[3],
               ab + (uint32_t)((arow*LDP + R + 16 + (((lane>>3)&1)<<3))<<1));
        #pragma unroll
        for (int j=0;j<4;j++){
          int brow = CW + (j<<4) + (lane&15);
          uint32_t b0,b1,b2,b3;
          ldsm4(b0,b1,b2,b3, bbs + (uint32_t)((brow*LDP + (kk<<4) + ((lane>>4)<<3))<<1));
          mma16816(acc[0][2*j],   A0[0],A0[1],A0[2],A0[3], b0,b2);
          mma16816(acc[0][2*j+1], A0[0],A0[1],A0[2],A0[3], b1,b3);
          mma16816(acc[1][2*j],   A1[0],A1[1],A1[2],A1[3], b0,b2);
          mma16816(acc[1][2*j+1], A1[0],A1[1],A1[2],A1[3], b1,b3);
        }
      }
    }
    __syncthreads();
  }

  const size_t rowbase = (size_t)b*NSEQ + n0;
  #pragma unroll
  for (int a2=0;a2<2;a2++){
    int row0 = R + a2*16 + (lane>>2);
    #pragma unroll
    for (int f=0; f<8; f++){
      int h = CW + (f<<3) + ((lane&3)<<1);
      float bv0 = bias[h], bv1 = bias[h+1];
      float m00=acc[a2][f][0]+bv0, m01=acc[a2][f][1]+bv1;
      float m10=acc[a2][f][2]+bv0, m11=acc[a2][f][3]+bv1;
      __nv_bfloat16 h00=__float2bfloat16(m00), h01=__float2bfloat16(m01);
      __nv_bfloat16 h10=__float2bfloat16(m10), h11=__float2bfloat16(m11);
      int o0 = (int)((rowbase + row0    )*HDIM) + h;
      int o1 = (int)((rowbase + row0 + 8)*HDIM) + h;
      *(uint32_t*)(Ohi+o0) = ((uint32_t)__bfloat16_as_ushort(h01)<<16)|__bfloat16_as_ushort(h00);
      *(uint32_t*)(Ohi+o1) = ((uint32_t)__bfloat16_as_ushort(h11)<<16)|__bfloat16_as_ushort(h10);
      *(uint32_t*)(Olo+o0) = packbf(m00-__bfloat162float(h00), m01-__bfloat162float(h01));
      *(uint32_t*)(Olo+o1) = packbf(m10-__bfloat162float(h10), m11-__bfloat162float(h11));
    }
  }
}

// ====================================================================
// Phase 2: per row n: rowsum = sum_x exp(S[n,x]), diag = exp(S[n,n])/rowsum.
// 8 warps (256 thr, 255 regs), warp tile 32x64 (R2 geometry — smem floor
// 4608cyc < MMA floor 6144cyc). Double accumulator sets: exp(tile j-1)
// overlaps MMA(tile j). ONE __syncthreads per tile.
// ====================================================================
static __device__ __forceinline__ void load_pair(uint32_t dh, uint32_t dl,
    const __nv_bfloat16* __restrict__ gh, const __nv_bfloat16* __restrict__ gl,
    size_t rowbase, int t)
{
  #pragma unroll
  for (int it=0; it<8; it++){
    int idx = t + (it<<8);               // 256 threads
    int row = idx>>4, hc = idx&15;
    uint32_t off = (uint32_t)((row*LDP + (hc<<3))<<1);
    cpa16(dh + off, gh + (rowbase+row)*HDIM + (hc<<3));
    cpa16(dl + off, gl + (rowbase+row)*HDIM + (hc<<3));
  }
}

__global__ void __launch_bounds__(256,1) attn_kernel()
{
  extern __shared__ __nv_bfloat16 sm2[];
  const uint32_t aHib = smem_u32(sm2);
  const uint32_t aLob = smem_u32(sm2 + TILEE);
  uint32_t sB_hi[2], sB_lo[2];
  sB_hi[0] = smem_u32(sm2 + 2*TILEE);
  sB_lo[0] = smem_u32(sm2 + 3*TILEE);
  sB_hi[1] = smem_u32(sm2 + 4*TILEE);
  sB_lo[1] = smem_u32(sm2 + 5*TILEE);
  __shared__ float sdiag[128];
  __shared__ float srow[128];

  const int t = threadIdx.x, warp = t>>5, lane = t&31;
  const int ntile = blockIdx.x, b = blockIdx.y;
  const int n0 = ntile*128;
  const size_t base = (size_t)b*NSEQ;
  const int R  = (warp>>1)*32;
  const int CW = (warp&1)*64;

  // prologue: A tile + B tile 0 (single commit group outstanding)
  load_pair(aHib, aLob, g_Ahi, g_Alo, base + n0, t);
  load_pair(sB_hi[0], sB_lo[0], g_Bhi, g_Blo, base, t);
  asm volatile("cp.async.commit_group;":::"memory");

  const int a_row  = (lane&7) + (((lane>>3)&1)<<3);
  const int k_off  = ((lane>>4)<<3);
  const int b_rowL = (lane&15);
  const int cb0    = ((lane&3)<<1);

  float acc[2][2][8][4];          // [bufset][A-half][col-block][frag]
  float rs[4] = {0.f,0.f,0.f,0.f};

  for (int j=0; j<32; j++){
    const int s = j&1;
    asm volatile("cp.async.wait_group 0;":::"memory");  // tile-j loads done
    __syncthreads();                                    // visible to all; all warps
                                                        // finished LDSM of tile j-1
    if (j+1 < 32){
      load_pair(sB_hi[s^1], sB_lo[s^1], g_Bhi, g_Blo, base + (size_t)(j+1)*128, t);
      asm volatile("cp.async.commit_group;":::"memory");
    }

    #pragma unroll
    for (int a=0;a<2;a++)
      #pragma unroll
      for (int f=0;f<8;f++){acc[s][a][f][0]=0.f;acc[s][a][f][1]=0.f;acc[s][a][f][2]=0.f;acc[s][a][f][3]=0.f;}

    // MMA tile j (bf16x3: hi*hi, hi*lo, lo*hi)
    #pragma unroll
    for (int seg=0; seg<3; seg++){
      uint32_t ab  = (seg==2)? aLob : aHib;
      uint32_t bbs = (seg==1)? sB_lo[s] : sB_hi[s];
      #pragma unroll
      for (int kk=0; kk<8; kk++){
        uint32_t A0[4], A1[4];
        ldsm4(A0[0],A0[1],A0[2],A0[3],
              ab + (uint32_t)(((R      + a_row)*LDP + (kk<<4) + k_off)<<1));
        ldsm4(A1[0],A1[1],A1[2],A1[3],
              ab + (uint32_t)(((R + 16 + a_row)*LDP + (kk<<4) + k_off)<<1));
        #pragma unroll
        for (int jj=0;jj<4;jj++){
          int brow = CW + (jj<<4) + b_rowL;
          uint32_t b0,b1,b2,b3;
          ldsm4(b0,b1,b2,b3, bbs + (uint32_t)((brow*LDP + (kk<<4) + k_off)<<1));
          mma16816(acc[s][0][2*jj],   A0[0],A0[1],A0[2],A0[3], b0,b2);
          mma16816(acc[s][0][2*jj+1], A0[0],A0[1],A0[2],A0[3], b1,b3);
          mma16816(acc[s][1][2*jj],   A1[0],A1[1],A1[2],A1[3], b0,b2);
          mma16816(acc[s][1][2*jj+1], A1[0],A1[1],A1[2],A1[3], b1,b3);
        }
      }
    }

    // exp + row-sum of PREVIOUS tile (overlaps this tile's MMA execution)
    if (j > 0){
      const int ps = s^1;
      const bool dg = ((j-1) == ntile);
      #pragma unroll
      for (int a2=0;a2<2;a2++){
        int r0 = R + a2*16 + (lane>>2);
        #pragma unroll
        for (int f=0; f<8; f++){
          float e0 = __expf(acc[ps][a2][f][0]);
          float e1 = __expf(acc[ps][a2][f][1]);
          float e2 = __expf(acc[ps][a2][f][2]);
          float e3 = __expf(acc[ps][a2][f][3]);
          rs[a2*2]   += e0 + e1;
          rs[a2*2+1] += e2 + e3;
          if (dg){
            int col = CW + (f<<3) + cb0;
            if (col   == r0  ) sdiag[r0]   = e0;
            if (col+1 == r0  ) sdiag[r0]   = e1;
            if (col   == r0+8) sdiag[r0+8] = e2;
            if (col+1 == r0+8) sdiag[r0+8] = e3;
          }
        }
      }
    }
  }

  // tail: exp of tile 31 (acc set 1)
  {
    const int ps = 1;
    const bool dg = (31 == ntile);
    #pragma unroll
    for (int a2=0;a2<2;a2++){
      int r0 = R + a2*16 + (lane>>2);
      #pragma unroll
      for (int f=0; f<8; f++){
        float e0 = __expf(acc[ps][a2][f][0]);
        float e1 = __expf(acc[ps][a2][f][1]);
        float e2 = __expf(acc[ps][a2][f][2]);
        float e3 = __expf(acc[ps][a2][f][3]);
        rs[a2*2]   += e0 + e1;
        rs[a2*2+1] += e2 + e3;
        if (dg){
          int col = CW + (f<<3) + cb0;
          if (col   == r0  ) sdiag[r0]   = e0;
          if (col+1 == r0  ) sdiag[r0]   = e1;
          if (col   == r0+8) sdiag[r0+8] = e2;
          if (col+1 == r0+8) sdiag[r0+8] = e3;
        }
      }
    }
  }

  // reduce row sums across the 4 column lanes
  #pragma unroll
  for (int q=0;q<4;q++){
    rs[q] += __shfl_xor_sync(0xffffffffu, rs[q], 1);
    rs[q] += __shfl_xor_sync(0xffffffffu, rs[q], 2);
  }
  // combine the two column-half warps via smem
  if ((warp&1)==0 && (lane&3)==0){
    int rr = lane>>2;
    #pragma unroll
    for (int q=0;q<4;q++) srow[R + q*8 + rr] = rs[q];
  }
  __syncthreads();
  if ((warp&1)==1 && (lane&3)==0){
    int rr = lane>>2;
    #pragma unroll
    for (int q=0;q<4;q++){
      int row = R + q*8 + rr;
      float tot = srow[row] + rs[q];
      g_diag[base + n0 + row] = sdiag[row] / tot;
    }
  }
}

// ====================================================================
// Phase 3: out_a = diag * input_b ; out_b = diag * input_a  (float4)
// ====================================================================
__global__ void __launch_bounds__(256) scale_kernel(
    const float* __restrict__ Xa, const float* __restrict__ Xb, float* __restrict__ out)
{
  const int NF4 = (BATCH*CCH*NSEQ)/4;
  const float4* A4 = (const float4*)Xa;
  const float4* B4 = (const float4*)Xb;
  const float4* D4 = (const float4*)g_diag;
  float4* O = (float4*)out;
  int stride = gridDim.x*blockDim.x;
  for (int i = blockIdx.x*blockDim.x + threadIdx.x; i < 2*NF4; i += stride){
    int sel = (i >= NF4);
    int j = sel ? i - NF4 : i;
    int n4 = j & (NSEQ/4 - 1);
    int bb = (j >> 10) >> 8;
    float4 d = D4[(bb<<10) + n4];
    float4 v = sel ? A4[j] : B4[j];
    float4 o; o.x=v.x*d.x; o.y=v.y*d.y; o.z=v.z*d.z; o.w=v.w*d.w;
    O[i] = o;
  }
}

extern "C" void kernel_launch(void* const* d_in, const int* in_sizes, int n_in,
                              void* d_out, int out_size) {
  const float* Xa = (const float*)d_in[0];
  const float* Xb = (const float*)d_in[1];
  const float* Wa = (const float*)d_in[2];
  const float* ba = (const float*)d_in[3];
  const float* Wb = (const float*)d_in[4];
  const float* bb = (const float*)d_in[5];
  float* out = (float*)d_out;

  const int SMEM_A = 4*TILEE*2;   // 139264 B
  const int SMEM_B = 6*TILEE*2;   // 208896 B
  cudaFuncSetAttribute(map_kernel,  cudaFuncAttributeMaxDynamicSharedMemorySize, SMEM_A);
  cudaFuncSetAttribute(attn_kernel, cudaFuncAttributeMaxDynamicSharedMemorySize, SMEM_B);

  dim3 ga(NSEQ/128, BATCH, 2);
  map_kernel<<<ga, 256, SMEM_A>>>(Xa, Xb, Wa, ba, Wb, bb);
  dim3 gb(NSEQ/128, BATCH);
  attn_kernel<<<gb, 256, SMEM_B>>>();
  scale_kernel<<<2048, 256>>>(Xa, Xb, out);
}

// round 8
// speedup vs baseline: 2.3096x; 1.3864x over previous
#include <cuda_runtime.h>
#include <cuda_bf16.h>
#include <cstdint>

#define BATCH 4
#define CCH   256
#define NSEQ  4096
#define HDIM  128
#define LDP   136                  // padded smem row stride for map kernel smem tiles
#define TILEE (128*LDP)
#define TB    32768                // bytes per 128x128 bf16 tile (contiguous, swizzled)

// ---------------- device scratch ----------------
// Layout of g_* : per batch, 32 tiles of 128 rows; within a tile, row-major
// 256B rows; within a row, 16B chunks XOR-swizzled: chunk' = chunk ^ (row&7).
__device__ __align__(16) __nv_bfloat16 g_Ahi[BATCH*NSEQ*HDIM];
__device__ __align__(16) __nv_bfloat16 g_Alo[BATCH*NSEQ*HDIM];
__device__ __align__(16) __nv_bfloat16 g_Bhi[BATCH*NSEQ*HDIM];
__device__ __align__(16) __nv_bfloat16 g_Blo[BATCH*NSEQ*HDIM];
__device__ __align__(16) float         g_diag[BATCH*NSEQ];

// ---------------- helpers ----------------
static __device__ __forceinline__ uint32_t smem_u32(const void* p){
  return (uint32_t)__cvta_generic_to_shared(p);
}
static __device__ __forceinline__ void ldsm4(uint32_t&r0,uint32_t&r1,uint32_t&r2,uint32_t&r3,uint32_t a){
  asm volatile("ldmatrix.sync.aligned.m8n8.x4.shared.b16 {%0,%1,%2,%3}, [%4];"
    : "=r"(r0),"=r"(r1),"=r"(r2),"=r"(r3) : "r"(a));
}
static __device__ __forceinline__ void ldsm4t(uint32_t&r0,uint32_t&r1,uint32_t&r2,uint32_t&r3,uint32_t a){
  asm volatile("ldmatrix.sync.aligned.m8n8.x4.trans.shared.b16 {%0,%1,%2,%3}, [%4];"
    : "=r"(r0),"=r"(r1),"=r"(r2),"=r"(r3) : "r"(a));
}
static __device__ __forceinline__ void mma16816(float* c,
    uint32_t a0,uint32_t a1,uint32_t a2,uint32_t a3,uint32_t b0,uint32_t b1){
  asm volatile("mma.sync.aligned.m16n8k16.row.col.f32.bf16.bf16.f32 "
    "{%0,%1,%2,%3}, {%4,%5,%6,%7}, {%8,%9}, {%0,%1,%2,%3};"
    : "+f"(c[0]),"+f"(c[1]),"+f"(c[2]),"+f"(c[3])
    : "r"(a0),"r"(a1),"r"(a2),"r"(a3),"r"(b0),"r"(b1));
}
static __device__ __forceinline__ uint32_t packbf(float x, float y){
  __nv_bfloat16 a=__float2bfloat16(x), b=__float2bfloat16(y);
  return ((uint32_t)__bfloat16_as_ushort(b)<<16)|(uint32_t)__bfloat16_as_ushort(a);
}
static __device__ __forceinline__ void split_store(__nv_bfloat16* hi, __nv_bfloat16* lo,
                                                   int off, float4 v){
  __nv_bfloat16 h0=__float2bfloat16(v.x),h1=__float2bfloat16(v.y);
  __nv_bfloat16 h2=__float2bfloat16(v.z),h3=__float2bfloat16(v.w);
  uint2 ph, pl;
  ph.x = ((uint32_t)__bfloat16_as_ushort(h1)<<16)|__bfloat16_as_ushort(h0);
  ph.y = ((uint32_t)__bfloat16_as_ushort(h3)<<16)|__bfloat16_as_ushort(h2);
  pl.x = packbf(v.x-__bfloat162float(h0), v.y-__bfloat162float(h1));
  pl.y = packbf(v.z-__bfloat162float(h2), v.w-__bfloat162float(h3));
  *(uint2*)(hi + off) = ph;
  *(uint2*)(lo + off) = pl;
}
static __device__ __forceinline__ void minit(uint32_t bar, uint32_t cnt){
  asm volatile("mbarrier.init.shared.b64 [%0], %1;" :: "r"(bar),"r"(cnt) : "memory");
}
static __device__ __forceinline__ void mexpect(uint32_t bar, uint32_t tx){
  asm volatile("mbarrier.arrive.expect_tx.shared.b64 _, [%0], %1;" :: "r"(bar),"r"(tx) : "memory");
}
static __device__ __forceinline__ void mwait(uint32_t bar, uint32_t ph){
  asm volatile("{\n\t.reg .pred P;\n\tWL%=:\n\t"
    "mbarrier.try_wait.parity.acquire.cta.shared::cta.b64 P, [%0], %1, 0x989680;\n\t"
    "@!P bra WL%=;\n\t}" :: "r"(bar),"r"(ph) : "memory");
}
static __device__ __forceinline__ void bulkcp(uint32_t dst, const void* src, uint32_t bytes, uint32_t bar){
  asm volatile("cp.async.bulk.shared::cta.global.mbarrier::complete_tx::bytes [%0], [%1], %2, [%3];"
    :: "r"(dst),"l"(src),"r"(bytes),"r"(bar) : "memory");
}

// ====================================================================
// Phase 1: mapping GEMM (R2 compute, epilogue writes swizzled layout).
// 8 warps, warp tile 32(n) x 64(h), bf16x3 split.
// ====================================================================
__global__ void __launch_bounds__(256) map_kernel(
    const float* __restrict__ Xa, const float* __restrict__ Xb,
    const float* __restrict__ Wa, const float* __restrict__ ba,
    const float* __restrict__ Wb, const float* __restrict__ bb)
{
  extern __shared__ __nv_bfloat16 sm[];
  __nv_bfloat16* sXhi = sm;
  __nv_bfloat16* sXlo = sm + TILEE;
  __nv_bfloat16* sWhi = sm + 2*TILEE;
  __nv_bfloat16* sWlo = sm + 3*TILEE;

  const int t = threadIdx.x, warp = t>>5, lane = t&31;
  const int ntile = blockIdx.x, b = blockIdx.y, sel = blockIdx.z;
  const float* X    = sel ? Xb : Xa;
  const float* W    = sel ? Wb : Wa;
  const float* bias = sel ? bb : ba;
  __nv_bfloat16* Ohi = sel ? g_Bhi : g_Ahi;
  __nv_bfloat16* Olo = sel ? g_Blo : g_Alo;
  const int n0 = ntile*128;
  const int R  = (warp>>1)*32;
  const int CW = (warp&1)*64;

  float acc[2][8][4];
  #pragma unroll
  for (int a=0;a<2;a++)
    #pragma unroll
    for (int f=0;f<8;f++){acc[a][f][0]=0.f;acc[a][f][1]=0.f;acc[a][f][2]=0.f;acc[a][f][3]=0.f;}

  for (int cc=0; cc<2; cc++){
    const float* src = X + ((size_t)b*CCH + (size_t)cc*128)*NSEQ + n0;
    #pragma unroll
    for (int it=0; it<16; it++){
      int idx = t + it*256;
      int row = idx>>5, c4 = idx&31;
      float4 v = *(const float4*)(src + (size_t)row*NSEQ + (c4<<2));
      split_store(sXhi, sXlo, row*LDP + (c4<<2), v);
    }
    const float* srcW = W + cc*128;
    #pragma unroll
    for (int it=0; it<16; it++){
      int idx = t + it*256;
      int row = idx>>5, c4 = idx&31;
      float4 v = *(const float4*)(srcW + (size_t)row*CCH + (c4<<2));
      split_store(sWhi, sWlo, row*LDP + (c4<<2), v);
    }
    __syncthreads();

    #pragma unroll
    for (int seg=0; seg<3; seg++){
      const __nv_bfloat16* A  = (seg==2)? sXlo : sXhi;
      const __nv_bfloat16* Bm = (seg==1)? sWlo : sWhi;
      uint32_t ab = smem_u32(A), bbs = smem_u32(Bm);
      #pragma unroll
      for (int kk=0; kk<8; kk++){
        int arow = (kk<<4) + (lane&7) + ((lane>>4)<<3);
        uint32_t A0[4], A1[4];
        ldsm4t(A0[0],A0[1],A0[2],A0[3],
               ab + (uint32_t)((arow*LDP + R      + (((lane>>3)&1)<<3))<<1));
        ldsm4t(A1[0],A1[1],A1[2],A1[3],
               ab + (uint32_t)((arow*LDP + R + 16 + (((lane>>3)&1)<<3))<<1));
        #pragma unroll
        for (int j=0;j<4;j++){
          int brow = CW + (j<<4) + (lane&15);
          uint32_t b0,b1,b2,b3;
          ldsm4(b0,b1,b2,b3, bbs + (uint32_t)((brow*LDP + (kk<<4) + ((lane>>4)<<3))<<1));
          mma16816(acc[0][2*j],   A0[0],A0[1],A0[2],A0[3], b0,b2);
          mma16816(acc[0][2*j+1], A0[0],A0[1],A0[2],A0[3], b1,b3);
          mma16816(acc[1][2*j],   A1[0],A1[1],A1[2],A1[3], b0,b2);
          mma16816(acc[1][2*j+1], A1[0],A1[1],A1[2],A1[3], b1,b3);
        }
      }
    }
    __syncthreads();
  }

  // epilogue: +bias, split hi/lo, store SWIZZLED:
  // elem offset = (globrow)*128 + ((h>>3)^(row&7))*8 + (h&7)
  const size_t rowbase = (size_t)b*NSEQ + n0;
  #pragma unroll
  for (int a2=0;a2<2;a2++){
    int row0 = R + a2*16 + (lane>>2);
    int sw = row0 & 7;                       // same for row0 and row0+8
    #pragma unroll
    for (int f=0; f<8; f++){
      int h = CW + (f<<3) + ((lane&3)<<1);
      int hpos = (((h>>3) ^ sw)<<3) + (h&7); // swizzled within-row elem offset
      float bv0 = bias[h], bv1 = bias[h+1];
      float m00=acc[a2][f][0]+bv0, m01=acc[a2][f][1]+bv1;
      float m10=acc[a2][f][2]+bv0, m11=acc[a2][f][3]+bv1;
      __nv_bfloat16 h00=__float2bfloat16(m00), h01=__float2bfloat16(m01);
      __nv_bfloat16 h10=__float2bfloat16(m10), h11=__float2bfloat16(m11);
      int o0 = (int)((rowbase + row0    )*HDIM) + hpos;
      int o1 = (int)((rowbase + row0 + 8)*HDIM) + hpos;
      *(uint32_t*)(Ohi+o0) = ((uint32_t)__bfloat16_as_ushort(h01)<<16)|__bfloat16_as_ushort(h00);
      *(uint32_t*)(Ohi+o1) = ((uint32_t)__bfloat16_as_ushort(h11)<<16)|__bfloat16_as_ushort(h10);
      *(uint32_t*)(Olo+o0) = packbf(m00-__bfloat162float(h00), m01-__bfloat162float(h01));
      *(uint32_t*)(Olo+o1) = packbf(m10-__bfloat162float(h10), m11-__bfloat162float(h11));
    }
  }
}

// ====================================================================
// Phase 2: per row n: rowsum = sum_x exp(S[n,x]), diag = exp(S[n,n])/rowsum.
// S = mapped_a . mapped_b^T (bf16x3, K=128). R2 geometry: 256 thr, 8 warps,
// warp tile 32x64, single acc set. Tiles fetched via cp.async.bulk (32KB
// each) from the pre-swizzled gmem layout -> near-zero LSU issue cost.
// ====================================================================
__global__ void __launch_bounds__(256,1) attn_kernel()
{
  extern __shared__ __nv_bfloat16 sm2[];
  const uint32_t sA_hi = smem_u32(sm2);                 // 6 x 32KB tiles
  const uint32_t sA_lo = sA_hi + TB;
  const uint32_t sB_hi0 = sA_hi + 2*TB, sB_lo0 = sA_hi + 3*TB;
  const uint32_t sB_hi1 = sA_hi + 4*TB, sB_lo1 = sA_hi + 5*TB;
  __shared__ __align__(8) unsigned long long s_bar[2];
  __shared__ float sdiag[128];
  __shared__ float srow[128];

  const int t = threadIdx.x, warp = t>>5, lane = t&31;
  const int ntile = blockIdx.x, b = blockIdx.y;
  const size_t ebase = (size_t)b*NSEQ*HDIM;             // elem base of batch
  const uint32_t bar[2] = { smem_u32(&s_bar[0]), smem_u32(&s_bar[1]) };
  const int R  = (warp>>1)*32;
  const int CW = (warp&1)*64;

  if (t == 0){ minit(bar[0],1); minit(bar[1],1); }
  __syncthreads();

  if (t == 0){
    // barrier0: A tile (hi+lo) + B tile 0 (hi+lo) = 4 x 32KB
    mexpect(bar[0], 4*TB);
    bulkcp(sA_hi,  g_Ahi + ebase + (size_t)ntile*128*HDIM, TB, bar[0]);
    bulkcp(sA_lo,  g_Alo + ebase + (size_t)ntile*128*HDIM, TB, bar[0]);
    bulkcp(sB_hi0, g_Bhi + ebase, TB, bar[0]);
    bulkcp(sB_lo0, g_Blo + ebase, TB, bar[0]);
  }

  const int s7  = lane & 7;      // swizzle bits (== row&7 of every fragment row)
  const int hi5 = lane >> 4;     // k-half select
  const int l15 = lane & 15;
  const int cb0 = ((lane&3)<<1);

  float acc[2][8][4];            // [A-half][col-block][frag] — 64 regs
  float rs[4] = {0.f,0.f,0.f,0.f};

  for (int j=0; j<32; j++){
    const int buf = j&1;
    mwait(bar[buf], (uint32_t)((j>>1)&1));
    __syncthreads();             // all warps past tile j-1's LDSMs; data visible

    if (t == 0 && j+1 < 32){     // refill the *other* buffer (held tile j-1)
      const int nb = buf^1;
      mexpect(bar[nb], 2*TB);
      bulkcp(nb ? sB_hi1 : sB_hi0, g_Bhi + ebase + (size_t)(j+1)*128*HDIM, TB, bar[nb]);
      bulkcp(nb ? sB_lo1 : sB_lo0, g_Blo + ebase + (size_t)(j+1)*128*HDIM, TB, bar[nb]);
    }

    #pragma unroll
    for (int a=0;a<2;a++)
      #pragma unroll
      for (int f=0;f<8;f++){acc[a][f][0]=0.f;acc[a][f][1]=0.f;acc[a][f][2]=0.f;acc[a][f][3]=0.f;}

    const uint32_t bHi = buf ? sB_hi1 : sB_hi0;
    const uint32_t bLo = buf ? sB_lo1 : sB_lo0;

    #pragma unroll
    for (int seg=0; seg<3; seg++){
      const uint32_t ab  = (seg==2)? sA_lo : sA_hi;
      const uint32_t bbs = (seg==1)? bLo : bHi;
      #pragma unroll
      for (int kk=0; kk<8; kk++){
        const uint32_t chsw = (uint32_t)((((kk<<1)|hi5) ^ s7) << 4);
        uint32_t A0[4], A1[4];
        ldsm4(A0[0],A0[1],A0[2],A0[3], ab + (uint32_t)((R      + l15)<<8) + chsw);
        ldsm4(A1[0],A1[1],A1[2],A1[3], ab + (uint32_t)((R + 16 + l15)<<8) + chsw);
        #pragma unroll
        for (int jj=0;jj<4;jj++){
          const int brow = CW + (jj<<4) + l15;
          uint32_t b0,b1,b2,b3;
          ldsm4(b0,b1,b2,b3, bbs + (uint32_t)(brow<<8) + chsw);
          mma16816(acc[0][2*jj],   A0[0],A0[1],A0[2],A0[3], b0,b2);
          mma16816(acc[0][2*jj+1], A0[0],A0[1],A0[2],A0[3], b1,b3);
          mma16816(acc[1][2*jj],   A1[0],A1[1],A1[2],A1[3], b0,b2);
          mma16816(acc[1][2*jj+1], A1[0],A1[1],A1[2],A1[3], b1,b3);
        }
      }
    }

    // exp + row-sum; capture diagonal on the matching tile
    const bool dg = (j == ntile);
    #pragma unroll
    for (int a2=0;a2<2;a2++){
      int r0 = R + a2*16 + (lane>>2);
      #pragma unroll
      for (int f=0; f<8; f++){
        float e0 = __expf(acc[a2][f][0]);
        float e1 = __expf(acc[a2][f][1]);
        float e2 = __expf(acc[a2][f][2]);
        float e3 = __expf(acc[a2][f][3]);
        rs[a2*2]   += e0 + e1;
        rs[a2*2+1] += e2 + e3;
        if (dg){
          int col = CW + (f<<3) + cb0;
          if (col   == r0  ) sdiag[r0]   = e0;
          if (col+1 == r0  ) sdiag[r0]   = e1;
          if (col   == r0+8) sdiag[r0+8] = e2;
          if (col+1 == r0+8) sdiag[r0+8] = e3;
        }
      }
    }
  }

  // reduce row sums across the 4 column lanes
  #pragma unroll
  for (int q=0;q<4;q++){
    rs[q] += __shfl_xor_sync(0xffffffffu, rs[q], 1);
    rs[q] += __shfl_xor_sync(0xffffffffu, rs[q], 2);
  }
  // combine the two column-half warps via smem
  if ((warp&1)==0 && (lane&3)==0){
    int rr = lane>>2;
    #pragma unroll
    for (int q=0;q<4;q++) srow[R + q*8 + rr] = rs[q];
  }
  __syncthreads();
  if ((warp&1)==1 && (lane&3)==0){
    int rr = lane>>2;
    #pragma unroll
    for (int q=0;q<4;q++){
      int row = R + q*8 + rr;
      float tot = srow[row] + rs[q];
      g_diag[(size_t)b*NSEQ + ntile*128 + row] = sdiag[row] / tot;
    }
  }
}

// ====================================================================
// Phase 3: out_a = diag * input_b ; out_b = diag * input_a  (float4)
// ====================================================================
__global__ void __launch_bounds__(256) scale_kernel(
    const float* __restrict__ Xa, const float* __restrict__ Xb, float* __restrict__ out)
{
  const int NF4 = (BATCH*CCH*NSEQ)/4;
  const float4* A4 = (const float4*)Xa;
  const float4* B4 = (const float4*)Xb;
  const float4* D4 = (const float4*)g_diag;
  float4* O = (float4*)out;
  int stride = gridDim.x*blockDim.x;
  for (int i = blockIdx.x*blockDim.x + threadIdx.x; i < 2*NF4; i += stride){
    int sel = (i >= NF4);
    int j = sel ? i - NF4 : i;
    int n4 = j & (NSEQ/4 - 1);
    int bb = (j >> 10) >> 8;
    float4 d = D4[(bb<<10) + n4];
    float4 v = sel ? A4[j] : B4[j];
    float4 o; o.x=v.x*d.x; o.y=v.y*d.y; o.z=v.z*d.z; o.w=v.w*d.w;
    O[i] = o;
  }
}

extern "C" void kernel_launch(void* const* d_in, const int* in_sizes, int n_in,
                              void* d_out, int out_size) {
  const float* Xa = (const float*)d_in[0];
  const float* Xb = (const float*)d_in[1];
  const float* Wa = (const float*)d_in[2];
  const float* ba = (const float*)d_in[3];
  const float* Wb = (const float*)d_in[4];
  const float* bb = (const float*)d_in[5];
  float* out = (float*)d_out;

  const int SMEM_A = 4*TILEE*2;   // 139264 B
  const int SMEM_B = 6*TB;        // 196608 B
  cudaFuncSetAttribute(map_kernel,  cudaFuncAttributeMaxDynamicSharedMemorySize, SMEM_A);
  cudaFuncSetAttribute(attn_kernel, cudaFuncAttributeMaxDynamicSharedMemorySize, SMEM_B);

  dim3 ga(NSEQ/128, BATCH, 2);
  map_kernel<<<ga, 256, SMEM_A>>>(Xa, Xb, Wa, ba, Wb, bb);
  dim3 gb(NSEQ/128, BATCH);
  attn_kernel<<<gb, 256, SMEM_B>>>();
  scale_kernel<<<2048, 256>>>(Xa, Xb, out);
}